// round 15
// baseline (speedup 1.0000x reference)
#include <cuda_runtime.h>
#include <cstdint>

// fastmax attention, b=4 h=16 n=1024 d=64.
// Round 14: R12 base + static 3-slot pipeline in main:
//   Ka/Kb: K double-buffer (compile-time-ish bases, cur=jt&1) - K wait free
//   VT:    transposed V single slot, issued at tile top, waited post-GEMM1
//   Ss:    relocated into the dead K slot after GEMM1 (no extra smem)
// -> 104.4KB smem, 2 CTAs/SM kept. Arithmetic bit-identical to R12.

#define B_  4
#define H_  16
#define N_  1024
#define D_  64
#define BH_ (B_*H_)

__device__ float g_qn [(size_t)BH_ * N_ * D_];          // fp32 normalized q
__device__ float g_knh[(size_t)BH_ * N_ * D_];          // tf32-hi of normalized k
__device__ float g_knl[(size_t)BH_ * N_ * D_];          // tf32-lo
__device__ float g_vth[(size_t)BH_ * D_ * N_];          // tf32-hi of (v+0.1n)^T [bh][d][j]
__device__ float g_vtl[(size_t)BH_ * D_ * N_];          // tf32-lo
__device__ float g_qr [(size_t)BH_ * N_ * N_];          // fp32 bias table (m-indexed)

// ---------------------------------------------------------------------------
__device__ __forceinline__ void split2(float x, uint32_t& hi, uint32_t& lo) {
    asm("cvt.rna.tf32.f32 %0, %1;" : "=r"(hi) : "f"(x));
    float r = x - __uint_as_float(hi);
    asm("cvt.rna.tf32.f32 %0, %1;" : "=r"(lo) : "f"(r));
}

__device__ __forceinline__ void mma_tf32(float c[4], const uint32_t a[4],
                                         uint32_t b0, uint32_t b1) {
    asm("mma.sync.aligned.m16n8k8.row.col.f32.tf32.tf32.f32 "
        "{%0,%1,%2,%3}, {%4,%5,%6,%7}, {%8,%9}, {%0,%1,%2,%3};"
        : "+f"(c[0]), "+f"(c[1]), "+f"(c[2]), "+f"(c[3])
        : "r"(a[0]), "r"(a[1]), "r"(a[2]), "r"(a[3]), "r"(b0), "r"(b1));
}

__device__ __forceinline__ void cp_async16(void* sdst, const void* gsrc) {
    uint32_t s = (uint32_t)__cvta_generic_to_shared(sdst);
    asm volatile("cp.async.cg.shared.global [%0], [%1], 16;" :: "r"(s), "l"(gsrc));
}

// ---------------------------------------------------------------------------
// prep: normalize q -> g_qn (fp32); normalize k -> split tf32 hi/lo
// ---------------------------------------------------------------------------
__global__ void prep_norm_kernel(const float* __restrict__ q,
                                 const float* __restrict__ k) {
    int gw   = (blockIdx.x * blockDim.x + threadIdx.x) >> 5;
    int lane = threadIdx.x & 31;
    const int total = BH_ * N_;
    const bool is_q = (gw < total);
    const int row = is_q ? gw : gw - total;
    const float* src = is_q ? q : k;
    const float2 v = reinterpret_cast<const float2*>(src + (size_t)row * D_)[lane];
    float ss = v.x * v.x + v.y * v.y;
    #pragma unroll
    for (int o = 16; o > 0; o >>= 1) ss += __shfl_xor_sync(0xffffffffu, ss, o);
    float inv = rsqrtf(ss);
    float x = v.x * inv, y = v.y * inv;
    if (is_q) {
        reinterpret_cast<float2*>(g_qn + (size_t)row * D_)[lane] = make_float2(x, y);
    } else {
        uint32_t xh, xl, yh, yl;
        split2(x, xh, xl);
        split2(y, yh, yl);
        reinterpret_cast<float2*>(g_knh + (size_t)row * D_)[lane] =
            make_float2(__uint_as_float(xh), __uint_as_float(yh));
        reinterpret_cast<float2*>(g_knl + (size_t)row * D_)[lane] =
            make_float2(__uint_as_float(xl), __uint_as_float(yl));
    }
}

// ---------------------------------------------------------------------------
// prep: Vp = v + 0.1*noise, transposed to [bh][d][j], split tf32 hi/lo
// ---------------------------------------------------------------------------
__global__ void __launch_bounds__(256) prep_vt_kernel(const float* __restrict__ v,
                                                      const float* __restrict__ nz) {
    __shared__ float tile[64][65];
    const int j0 = blockIdx.x * 64;
    const int bh = blockIdx.y;
    const int tid = threadIdx.x;
    const float* vs = v  + ((size_t)bh * N_ + j0) * D_;
    const float* ns = nz + ((size_t)bh * N_ + j0) * D_;
    #pragma unroll
    for (int e = tid; e < 1024; e += 256) {
        int r = e >> 4, c = (e & 15) << 2;
        float4 a = *reinterpret_cast<const float4*>(vs + r * D_ + c);
        float4 b = *reinterpret_cast<const float4*>(ns + r * D_ + c);
        tile[r][c + 0] = fmaf(0.1f, b.x, a.x);
        tile[r][c + 1] = fmaf(0.1f, b.y, a.y);
        tile[r][c + 2] = fmaf(0.1f, b.z, a.z);
        tile[r][c + 3] = fmaf(0.1f, b.w, a.w);
    }
    __syncthreads();
    #pragma unroll
    for (int e = tid; e < 1024; e += 256) {
        int d = e >> 4, j = (e & 15) << 2;
        float4 h, l;
        uint32_t th, tl;
        split2(tile[j + 0][d], th, tl); h.x = __uint_as_float(th); l.x = __uint_as_float(tl);
        split2(tile[j + 1][d], th, tl); h.y = __uint_as_float(th); l.y = __uint_as_float(tl);
        split2(tile[j + 2][d], th, tl); h.z = __uint_as_float(th); l.z = __uint_as_float(tl);
        split2(tile[j + 3][d], th, tl); h.w = __uint_as_float(th); l.w = __uint_as_float(tl);
        size_t off = ((size_t)bh * D_ + d) * N_ + j0 + j;
        *reinterpret_cast<float4*>(g_vth + off) = h;
        *reinterpret_cast<float4*>(g_vtl + off) = l;
    }
}

// ---------------------------------------------------------------------------
// QR[bh][i][m] = Qn_i . rpe2[m], 128x64 tiles via 3xTF32 mma. (R12 version)
// ---------------------------------------------------------------------------
__global__ void __launch_bounds__(256) qr_mma_kernel(const float* __restrict__ rpe) {
    const int mx = blockIdx.x, iy = blockIdx.y, bh = blockIdx.z;
    if (mx > 2 * iy + 1) return;

    extern __shared__ float sm[];
    float* Qs  = sm;              // [128][68] fp32
    float* Rsh = sm + 8704;       // [64][68] tf32-hi of rpe tile
    float* Rsl = sm + 13056;      // [64][68] tf32-lo

    const int tid = threadIdx.x;
    const int w = tid >> 5, lane = tid & 31;
    const int g = lane >> 2, l = lane & 3;
    const int i0 = iy * 128, m0 = mx * 64;

    const float* qsrc = g_qn + ((size_t)bh * N_ + i0) * D_;
    #pragma unroll
    for (int e = tid; e < 2048; e += 256) {
        int r = e >> 4, c = (e & 15) << 2;
        *reinterpret_cast<float4*>(Qs + r * 68 + c) =
            *reinterpret_cast<const float4*>(qsrc + r * 64 + c);
    }
    const float* rsrc = rpe + (size_t)(N_ - 1 + m0) * D_;
    #pragma unroll
    for (int e = tid; e < 1024; e += 256) {
        int r = e >> 4, c = (e & 15) << 2;
        float4 x = *reinterpret_cast<const float4*>(rsrc + r * 64 + c);
        float4 hh, ll;
        uint32_t th, tl;
        split2(x.x, th, tl); hh.x = __uint_as_float(th); ll.x = __uint_as_float(tl);
        split2(x.y, th, tl); hh.y = __uint_as_float(th); ll.y = __uint_as_float(tl);
        split2(x.z, th, tl); hh.z = __uint_as_float(th); ll.z = __uint_as_float(tl);
        split2(x.w, th, tl); hh.w = __uint_as_float(th); ll.w = __uint_as_float(tl);
        *reinterpret_cast<float4*>(Rsh + r * 68 + c) = hh;
        *reinterpret_cast<float4*>(Rsl + r * 68 + c) = ll;
    }
    __syncthreads();

    const int r0 = w * 16 + g;
    uint32_t qah[8][4], qal[8][4];
    #pragma unroll
    for (int kk = 0; kk < 8; kk++) {
        split2(Qs[r0 * 68 + kk * 8 + l],           qah[kk][0], qal[kk][0]);
        split2(Qs[(r0 + 8) * 68 + kk * 8 + l],     qah[kk][1], qal[kk][1]);
        split2(Qs[r0 * 68 + kk * 8 + l + 4],       qah[kk][2], qal[kk][2]);
        split2(Qs[(r0 + 8) * 68 + kk * 8 + l + 4], qah[kk][3], qal[kk][3]);
    }

    float acc[8][4] = {};
    #pragma unroll
    for (int kk = 0; kk < 8; kk++)
        #pragma unroll
        for (int n = 0; n < 8; n++) {
            const int o0 = (n * 8 + g) * 68 + kk * 8 + l;
            uint32_t bh0 = __float_as_uint(Rsh[o0]);
            uint32_t bh1 = __float_as_uint(Rsh[o0 + 4]);
            uint32_t bl0 = __float_as_uint(Rsl[o0]);
            uint32_t bl1 = __float_as_uint(Rsl[o0 + 4]);
            mma_tf32(acc[n], qah[kk], bh0, bh1);
            mma_tf32(acc[n], qal[kk], bh0, bh1);
            mma_tf32(acc[n], qah[kk], bl0, bl1);
        }

    float* dst = g_qr + (size_t)bh * N_ * N_;
    const int i_lo = i0 + r0, i_hi = i_lo + 8;
    #pragma unroll
    for (int n = 0; n < 8; n++) {
        int mc = m0 + n * 8 + 2 * l;
        *reinterpret_cast<float2*>(dst + (size_t)i_lo * N_ + mc) =
            make_float2(acc[n][0], acc[n][1]);
        *reinterpret_cast<float2*>(dst + (size_t)i_hi * N_ + mc) =
            make_float2(acc[n][2], acc[n][3]);
    }
}

// ---------------------------------------------------------------------------
// Main fused attention: block = (bh, 64-row i-tile), 4 warps, 2 CTAs/SM.
// Slots: Ka/Kb (K hi|lo, double-buffered), VT (V^T hi|lo, single).
// Per tile: [VT(t) issue] gather -> wait1 -> GEMM1(Kc) -> sync ->
//           [K(t+1)->Kn issue] epilogue(S -> Kc) -> wait -> GEMM2(Kc,VT) -> sync
// ---------------------------------------------------------------------------
__global__ void __launch_bounds__(128, 2) fastmax_mma_kernel(float* __restrict__ out) {
    extern __shared__ float sm[];
    float* Ka = sm;                  // [64][68] Kh | [64][68] Kl
    float* Kb = sm + 8704;
    float* VT = sm + 17408;          // [64][68] VTh | [64][68] VTl ; Q staging

    const int it = 15 - blockIdx.x;  // heavy tiles first
    const int bh = blockIdx.y;
    const int i0 = it * 64;

    const int tid = threadIdx.x;
    const int w = tid >> 5, lane = tid & 31;
    const int g = lane >> 2, l = lane & 3;
    const int r0 = w * 16 + g;

    const size_t gb  = (size_t)bh * N_ * D_;   // K base ([j][d])
    const size_t gvt = (size_t)bh * D_ * N_;   // VT base ([d][j])

    auto copyK = [&](int j0, float* dst) {
        const float* kh = g_knh + gb + (size_t)j0 * D_;
        const float* kl = g_knl + gb + (size_t)j0 * D_;
        #pragma unroll
        for (int e = tid; e < 1024; e += 128) {
            int r = e >> 4, c = (e & 15) << 2;
            cp_async16(dst + r * 68 + c,        kh + r * 64 + c);
            cp_async16(dst + 4352 + r * 68 + c, kl + r * 64 + c);
        }
    };
    auto copyVT = [&](int j0) {
        const float* vh = g_vth + gvt + j0;
        const float* vl = g_vtl + gvt + j0;
        #pragma unroll
        for (int e = tid; e < 1024; e += 128) {
            int r = e >> 4, c = (e & 15) << 2;
            cp_async16(VT + r * 68 + c,        vh + (size_t)r * N_ + c);
            cp_async16(VT + 4352 + r * 68 + c, vl + (size_t)r * N_ + c);
        }
    };

    // prologue: K(0) -> Ka
    copyK(0, Ka);
    asm volatile("cp.async.commit_group;");

    // Q staged through the VT slot (loop's first VT copy comes after sync)
    const float* qsrc = g_qn + gb + (size_t)i0 * D_;
    #pragma unroll
    for (int e = tid; e < 1024; e += 128) {
        int r = e >> 4, c = (e & 15) << 2;
        *reinterpret_cast<float4*>(VT + r * 68 + c) =
            *reinterpret_cast<const float4*>(qsrc + r * 64 + c);
    }
    __syncthreads();

    uint32_t qah[8][4], qal[8][4];
    #pragma unroll
    for (int kk = 0; kk < 8; kk++) {
        split2(VT[r0 * 68 + kk * 8 + l],           qah[kk][0], qal[kk][0]);
        split2(VT[(r0 + 8) * 68 + kk * 8 + l],     qah[kk][1], qal[kk][1]);
        split2(VT[r0 * 68 + kk * 8 + l + 4],       qah[kk][2], qal[kk][2]);
        split2(VT[(r0 + 8) * 68 + kk * 8 + l + 4], qah[kk][3], qal[kk][3]);
    }
    __syncthreads();   // Q reads done before VT copies overwrite

    const int i_lo = i0 + r0, i_hi = i_lo + 8;
    const float* qlo = g_qr + (size_t)bh * N_ * N_ + (size_t)i_lo * (N_ + 1);
    const float* qhi = g_qr + (size_t)bh * N_ * N_ + (size_t)i_hi * (N_ + 1);

    float oacc[8][4] = {};
    float dp_lo = 0.0f, dp_hi = 0.0f;

    const int njt = it + 1;
    for (int jt = 0; jt < njt; jt++) {
        const int j0 = jt * 64;
        float* Kc = (jt & 1) ? Kb : Ka;
        float* Kn = (jt & 1) ? Ka : Kb;

        // issue VT(t); pending groups: [K(t), VT(t)]
        copyVT(j0);
        asm volatile("cp.async.commit_group;");

        // bias gather overlaps in-flight copies
        const bool full = (jt < it);
        float qrv[8][4];
        #pragma unroll
        for (int n = 0; n < 8; n++) {
            int jc = j0 + n * 8 + 2 * l;
            if (full) {
                qrv[n][0] = __ldg(qlo - jc);
                qrv[n][1] = __ldg(qlo - (jc + 1));
                qrv[n][2] = __ldg(qhi - jc);
                qrv[n][3] = __ldg(qhi - (jc + 1));
            } else {
                qrv[n][0] = (jc     <= i_lo) ? __ldg(qlo - jc)       : 0.0f;
                qrv[n][1] = (jc + 1 <= i_lo) ? __ldg(qlo - (jc + 1)) : 0.0f;
                qrv[n][2] = (jc     <= i_hi) ? __ldg(qhi - jc)       : 0.0f;
                qrv[n][3] = (jc + 1 <= i_hi) ? __ldg(qhi - (jc + 1)) : 0.0f;
            }
        }

        // K(t) ready (VT may still be in flight)
        asm volatile("cp.async.wait_group 1;");
        __syncthreads();

        // GEMM1: S = Q . K^T  (3xTF32, pure LDS+HMMA)
        const float* Kh = Kc;
        const float* Kl = Kc + 4352;
        float sacc[8][4] = {};
        #pragma unroll
        for (int kk = 0; kk < 8; kk++)
            #pragma unroll
            for (int n = 0; n < 8; n++) {
                const int o0 = (n * 8 + g) * 68 + kk * 8 + l;
                uint32_t bh0 = __float_as_uint(Kh[o0]);
                uint32_t bh1 = __float_as_uint(Kh[o0 + 4]);
                uint32_t bl0 = __float_as_uint(Kl[o0]);
                uint32_t bl1 = __float_as_uint(Kl[o0 + 4]);
                mma_tf32(sacc[n], qah[kk], bh0, bh1);
                mma_tf32(sacc[n], qal[kk], bh0, bh1);
                mma_tf32(sacc[n], qah[kk], bl0, bl1);
            }
        __syncthreads();   // all warps done reading Kc before S is staged there

        // issue K(t+1) into the other slot; pending: [VT(t), K(t+1)]
        if (jt + 1 < njt) {
            copyK(j0 + 64, Kn);
            asm volatile("cp.async.commit_group;");
        }

        // Epilogue: +1, bias, causal mask, denom partials; stage S into Kc
        float* Ss = Kc;    // dead K slot, first 4352 floats
        #pragma unroll
        for (int n = 0; n < 8; n++) {
            int jc = j0 + n * 8 + 2 * l;
            float v00, v01, v10, v11;
            if (full) {
                v00 = sacc[n][0] + 1.0f + qrv[n][0];
                v01 = sacc[n][1] + 1.0f + qrv[n][1];
                v10 = sacc[n][2] + 1.0f + qrv[n][2];
                v11 = sacc[n][3] + 1.0f + qrv[n][3];
            } else {
                v00 = (jc     <= i_lo) ? sacc[n][0] + 1.0f + qrv[n][0] : 0.0f;
                v01 = (jc + 1 <= i_lo) ? sacc[n][1] + 1.0f + qrv[n][1] : 0.0f;
                v10 = (jc     <= i_hi) ? sacc[n][2] + 1.0f + qrv[n][2] : 0.0f;
                v11 = (jc + 1 <= i_hi) ? sacc[n][3] + 1.0f + qrv[n][3] : 0.0f;
            }
            dp_lo += v00 + v01;
            dp_hi += v10 + v11;
            *reinterpret_cast<float2*>(Ss + r0 * 68 + n * 8 + 2 * l) =
                make_float2(v00, v01);
            *reinterpret_cast<float2*>(Ss + (r0 + 8) * 68 + n * 8 + 2 * l) =
                make_float2(v10, v11);
        }

        // VT(t) ready (K(t+1) may still fly); also publishes Ss to the block
        if (jt + 1 < njt) {
            asm volatile("cp.async.wait_group 1;");
        } else {
            asm volatile("cp.async.wait_group 0;");
        }
        __syncthreads();

        // GEMM2: O += S . V  (A = S split on load from Kc; B = VT, K-style index)
        const float* Vh = VT;
        const float* Vl = VT + 4352;
        #pragma unroll
        for (int kk = 0; kk < 8; kk++) {
            uint32_t ah[4], al[4];
            split2(Ss[r0 * 68 + kk * 8 + l],           ah[0], al[0]);
            split2(Ss[(r0 + 8) * 68 + kk * 8 + l],     ah[1], al[1]);
            split2(Ss[r0 * 68 + kk * 8 + l + 4],       ah[2], al[2]);
            split2(Ss[(r0 + 8) * 68 + kk * 8 + l + 4], ah[3], al[3]);
            #pragma unroll
            for (int n = 0; n < 8; n++) {
                const int o0 = (n * 8 + g) * 68 + kk * 8 + l;
                uint32_t bh0 = __float_as_uint(Vh[o0]);
                uint32_t bh1 = __float_as_uint(Vh[o0 + 4]);
                uint32_t bl0 = __float_as_uint(Vl[o0]);
                uint32_t bl1 = __float_as_uint(Vl[o0 + 4]);
                mma_tf32(oacc[n], ah, bh0, bh1);
                mma_tf32(oacc[n], al, bh0, bh1);
                mma_tf32(oacc[n], ah, bl0, bl1);
            }
        }

        __syncthreads();   // GEMM2 done before next iter's VT copy overwrites
    }

    // Row denominators: reduce across the 4 lanes of each quad
    dp_lo += __shfl_xor_sync(0xffffffffu, dp_lo, 1);
    dp_lo += __shfl_xor_sync(0xffffffffu, dp_lo, 2);
    dp_hi += __shfl_xor_sync(0xffffffffu, dp_hi, 1);
    dp_hi += __shfl_xor_sync(0xffffffffu, dp_hi, 2);
    const float rlo = 1.0f / dp_lo;
    const float rhi = 1.0f / dp_hi;

    float* olo = out + ((size_t)bh * N_ + i_lo) * D_;
    float* ohi = out + ((size_t)bh * N_ + i_hi) * D_;
    #pragma unroll
    for (int n = 0; n < 8; n++) {
        int dc = n * 8 + 2 * l;
        *reinterpret_cast<float2*>(olo + dc) =
            make_float2(oacc[n][0] * rlo, oacc[n][1] * rlo);
        *reinterpret_cast<float2*>(ohi + dc) =
            make_float2(oacc[n][2] * rhi, oacc[n][3] * rhi);
    }
}

// ---------------------------------------------------------------------------
extern "C" void kernel_launch(void* const* d_in, const int* in_sizes, int n_in,
                              void* d_out, int out_size) {
    const float* q   = (const float*)d_in[0];
    const float* k   = (const float*)d_in[1];
    const float* v   = (const float*)d_in[2];
    const float* dn  = (const float*)d_in[3];
    const float* rpe = (const float*)d_in[4];
    float* out = (float*)d_out;

    prep_norm_kernel<<<(2 * BH_ * N_) / 8, 256>>>(q, k);
    prep_vt_kernel<<<dim3(N_ / 64, BH_), 256>>>(v, dn);

    const int qr_smem = (8704 + 2 * 4352) * sizeof(float);          // 69632 B
    cudaFuncSetAttribute(qr_mma_kernel,
                         cudaFuncAttributeMaxDynamicSharedMemorySize, qr_smem);
    qr_mma_kernel<<<dim3(16, 8, BH_), 256, qr_smem>>>(rpe);

    const int mn_smem = (3 * 8704) * sizeof(float);                 // 104448 B
    cudaFuncSetAttribute(fastmax_mma_kernel,
                         cudaFuncAttributeMaxDynamicSharedMemorySize, mn_smem);
    fastmax_mma_kernel<<<dim3(16, BH_), 128, mn_smem>>>(out);
}

// round 16
// speedup vs baseline: 1.2826x; 1.2826x over previous
#include <cuda_runtime.h>
#include <cstdint>

// fastmax attention, b=4 h=16 n=1024 d=64.
// Round 15: occupancy diet -> 3 CTAs/SM (12 warps) for the main kernel:
//   __launch_bounds__(128,3); bias gather moved to epilogue (frees 32 regs);
//   smem 69.6KB: Q staged via VT slot, V transposed single pair, S staged
//   into dead K slot after GEMM1. Arithmetic bit-identical to R10/R12.

#define B_  4
#define H_  16
#define N_  1024
#define D_  64
#define BH_ (B_*H_)

__device__ float g_qn [(size_t)BH_ * N_ * D_];          // fp32 normalized q
__device__ float g_knh[(size_t)BH_ * N_ * D_];          // tf32-hi of normalized k
__device__ float g_knl[(size_t)BH_ * N_ * D_];          // tf32-lo
__device__ float g_vth[(size_t)BH_ * D_ * N_];          // tf32-hi of (v+0.1n)^T [bh][d][j]
__device__ float g_vtl[(size_t)BH_ * D_ * N_];          // tf32-lo
__device__ float g_qr [(size_t)BH_ * N_ * N_];          // fp32 bias table (m-indexed)

// ---------------------------------------------------------------------------
__device__ __forceinline__ void split2(float x, uint32_t& hi, uint32_t& lo) {
    asm("cvt.rna.tf32.f32 %0, %1;" : "=r"(hi) : "f"(x));
    float r = x - __uint_as_float(hi);
    asm("cvt.rna.tf32.f32 %0, %1;" : "=r"(lo) : "f"(r));
}

__device__ __forceinline__ void mma_tf32(float c[4], const uint32_t a[4],
                                         uint32_t b0, uint32_t b1) {
    asm("mma.sync.aligned.m16n8k8.row.col.f32.tf32.tf32.f32 "
        "{%0,%1,%2,%3}, {%4,%5,%6,%7}, {%8,%9}, {%0,%1,%2,%3};"
        : "+f"(c[0]), "+f"(c[1]), "+f"(c[2]), "+f"(c[3])
        : "r"(a[0]), "r"(a[1]), "r"(a[2]), "r"(a[3]), "r"(b0), "r"(b1));
}

// 3xTF32 with full-fp32 B split on load (qr kernel only)
__device__ __forceinline__ void mma3(float c[4],
                                     const uint32_t ah[4], const uint32_t al[4],
                                     float b0f, float b1f) {
    uint32_t bh0, bl0, bh1, bl1;
    split2(b0f, bh0, bl0);
    split2(b1f, bh1, bl1);
    mma_tf32(c, ah, bh0, bh1);
    mma_tf32(c, al, bh0, bh1);
    mma_tf32(c, ah, bl0, bl1);
}

__device__ __forceinline__ void cp_async16(void* sdst, const void* gsrc) {
    uint32_t s = (uint32_t)__cvta_generic_to_shared(sdst);
    asm volatile("cp.async.cg.shared.global [%0], [%1], 16;" :: "r"(s), "l"(gsrc));
}

// ---------------------------------------------------------------------------
// prep: normalize q -> g_qn (fp32); normalize k -> split tf32 hi/lo
// ---------------------------------------------------------------------------
__global__ void prep_norm_kernel(const float* __restrict__ q,
                                 const float* __restrict__ k) {
    int gw   = (blockIdx.x * blockDim.x + threadIdx.x) >> 5;
    int lane = threadIdx.x & 31;
    const int total = BH_ * N_;
    const bool is_q = (gw < total);
    const int row = is_q ? gw : gw - total;
    const float* src = is_q ? q : k;
    const float2 v = reinterpret_cast<const float2*>(src + (size_t)row * D_)[lane];
    float ss = v.x * v.x + v.y * v.y;
    #pragma unroll
    for (int o = 16; o > 0; o >>= 1) ss += __shfl_xor_sync(0xffffffffu, ss, o);
    float inv = rsqrtf(ss);
    float x = v.x * inv, y = v.y * inv;
    if (is_q) {
        reinterpret_cast<float2*>(g_qn + (size_t)row * D_)[lane] = make_float2(x, y);
    } else {
        uint32_t xh, xl, yh, yl;
        split2(x, xh, xl);
        split2(y, yh, yl);
        reinterpret_cast<float2*>(g_knh + (size_t)row * D_)[lane] =
            make_float2(__uint_as_float(xh), __uint_as_float(yh));
        reinterpret_cast<float2*>(g_knl + (size_t)row * D_)[lane] =
            make_float2(__uint_as_float(xl), __uint_as_float(yl));
    }
}

// ---------------------------------------------------------------------------
// prep: Vp = v + 0.1*noise, transposed to [bh][d][j], split tf32 hi/lo
// ---------------------------------------------------------------------------
__global__ void __launch_bounds__(256) prep_vt_kernel(const float* __restrict__ v,
                                                      const float* __restrict__ nz) {
    __shared__ float tile[64][65];
    const int j0 = blockIdx.x * 64;
    const int bh = blockIdx.y;
    const int tid = threadIdx.x;
    const float* vs = v  + ((size_t)bh * N_ + j0) * D_;
    const float* ns = nz + ((size_t)bh * N_ + j0) * D_;
    #pragma unroll
    for (int e = tid; e < 1024; e += 256) {
        int r = e >> 4, c = (e & 15) << 2;
        float4 a = *reinterpret_cast<const float4*>(vs + r * D_ + c);
        float4 b = *reinterpret_cast<const float4*>(ns + r * D_ + c);
        tile[r][c + 0] = fmaf(0.1f, b.x, a.x);
        tile[r][c + 1] = fmaf(0.1f, b.y, a.y);
        tile[r][c + 2] = fmaf(0.1f, b.z, a.z);
        tile[r][c + 3] = fmaf(0.1f, b.w, a.w);
    }
    __syncthreads();
    #pragma unroll
    for (int e = tid; e < 1024; e += 256) {
        int d = e >> 4, j = (e & 15) << 2;
        float4 h, l;
        uint32_t th, tl;
        split2(tile[j + 0][d], th, tl); h.x = __uint_as_float(th); l.x = __uint_as_float(tl);
        split2(tile[j + 1][d], th, tl); h.y = __uint_as_float(th); l.y = __uint_as_float(tl);
        split2(tile[j + 2][d], th, tl); h.z = __uint_as_float(th); l.z = __uint_as_float(tl);
        split2(tile[j + 3][d], th, tl); h.w = __uint_as_float(th); l.w = __uint_as_float(tl);
        size_t off = ((size_t)bh * D_ + d) * N_ + j0 + j;
        *reinterpret_cast<float4*>(g_vth + off) = h;
        *reinterpret_cast<float4*>(g_vtl + off) = l;
    }
}

// ---------------------------------------------------------------------------
// QR[bh][i][m] = Qn_i . rpe2[m], 128x64 tiles via 3xTF32 mma. (R10 version)
// ---------------------------------------------------------------------------
__global__ void __launch_bounds__(256) qr_mma_kernel(const float* __restrict__ rpe) {
    const int mx = blockIdx.x, iy = blockIdx.y, bh = blockIdx.z;
    if (mx > 2 * iy + 1) return;

    extern __shared__ float sm[];
    float* Qs = sm;              // [128][68]
    float* Rs = sm + 128 * 68;   // [64][68]

    const int tid = threadIdx.x;
    const int w = tid >> 5, lane = tid & 31;
    const int g = lane >> 2, l = lane & 3;
    const int i0 = iy * 128, m0 = mx * 64;

    const float* qsrc = g_qn + ((size_t)bh * N_ + i0) * D_;
    #pragma unroll
    for (int e = tid; e < 2048; e += 256) {
        int r = e >> 4, c = (e & 15) << 2;
        *reinterpret_cast<float4*>(Qs + r * 68 + c) =
            *reinterpret_cast<const float4*>(qsrc + r * 64 + c);
    }
    const float* rsrc = rpe + (size_t)(N_ - 1 + m0) * D_;
    #pragma unroll
    for (int e = tid; e < 1024; e += 256) {
        int r = e >> 4, c = (e & 15) << 2;
        *reinterpret_cast<float4*>(Rs + r * 68 + c) =
            *reinterpret_cast<const float4*>(rsrc + r * 64 + c);
    }
    __syncthreads();

    const int r0 = w * 16 + g;
    float acc[8][4] = {};
    #pragma unroll
    for (int kk = 0; kk < 8; kk++) {
        uint32_t ah[4], al[4];
        split2(Qs[r0 * 68 + kk * 8 + l],           ah[0], al[0]);
        split2(Qs[(r0 + 8) * 68 + kk * 8 + l],     ah[1], al[1]);
        split2(Qs[r0 * 68 + kk * 8 + l + 4],       ah[2], al[2]);
        split2(Qs[(r0 + 8) * 68 + kk * 8 + l + 4], ah[3], al[3]);
        #pragma unroll
        for (int n = 0; n < 8; n++) {
            float b0 = Rs[(n * 8 + g) * 68 + kk * 8 + l];
            float b1 = Rs[(n * 8 + g) * 68 + kk * 8 + l + 4];
            mma3(acc[n], ah, al, b0, b1);
        }
    }

    float* dst = g_qr + (size_t)bh * N_ * N_;
    const int i_lo = i0 + r0, i_hi = i_lo + 8;
    #pragma unroll
    for (int n = 0; n < 8; n++) {
        int mc = m0 + n * 8 + 2 * l;
        *reinterpret_cast<float2*>(dst + (size_t)i_lo * N_ + mc) =
            make_float2(acc[n][0], acc[n][1]);
        *reinterpret_cast<float2*>(dst + (size_t)i_hi * N_ + mc) =
            make_float2(acc[n][2], acc[n][3]);
    }
}

// ---------------------------------------------------------------------------
// Main fused attention: block = (bh, 64-row i-tile), 4 warps, 3 CTAs/SM.
// smem (69.6KB): Kh|Kl (8704 fl) + VTh|VTl (8704 fl). Q staged via VT slot.
// Per tile: issue K+VT -> wait -> GEMM1 -> sync -> epilogue (bias LDG, mask,
// rowsum, S into dead K slot) -> GEMM2(S, VT) -> sync.
// ---------------------------------------------------------------------------
__global__ void __launch_bounds__(128, 3) fastmax_mma_kernel(float* __restrict__ out) {
    extern __shared__ float sm[];
    float* Kh = sm;                  // [64][68]
    float* Kl = sm + 4352;           // [64][68]
    float* VT = sm + 8704;           // [64][68] VTh | [64][68] VTl ; Q staging

    const int it = 15 - blockIdx.x;  // heavy tiles first
    const int bh = blockIdx.y;
    const int i0 = it * 64;

    const int tid = threadIdx.x;
    const int w = tid >> 5, lane = tid & 31;
    const int g = lane >> 2, l = lane & 3;
    const int r0 = w * 16 + g;

    const size_t gb  = (size_t)bh * N_ * D_;   // K base ([j][d])
    const size_t gvt = (size_t)bh * D_ * N_;   // VT base ([d][j])

    // Q staged through the VT slot, fragments extracted to registers
    const float* qsrc = g_qn + gb + (size_t)i0 * D_;
    #pragma unroll
    for (int e = tid; e < 1024; e += 128) {
        int r = e >> 4, c = (e & 15) << 2;
        *reinterpret_cast<float4*>(VT + r * 68 + c) =
            *reinterpret_cast<const float4*>(qsrc + r * 64 + c);
    }
    __syncthreads();

    uint32_t qah[8][4], qal[8][4];
    #pragma unroll
    for (int kk = 0; kk < 8; kk++) {
        split2(VT[r0 * 68 + kk * 8 + l],           qah[kk][0], qal[kk][0]);
        split2(VT[(r0 + 8) * 68 + kk * 8 + l],     qah[kk][1], qal[kk][1]);
        split2(VT[r0 * 68 + kk * 8 + l + 4],       qah[kk][2], qal[kk][2]);
        split2(VT[(r0 + 8) * 68 + kk * 8 + l + 4], qah[kk][3], qal[kk][3]);
    }
    __syncthreads();   // Q reads done before VT copies overwrite

    const int i_lo = i0 + r0, i_hi = i_lo + 8;
    const float* qlo = g_qr + (size_t)bh * N_ * N_ + (size_t)i_lo * (N_ + 1);
    const float* qhi = g_qr + (size_t)bh * N_ * N_ + (size_t)i_hi * (N_ + 1);

    float oacc[8][4] = {};
    float dp_lo = 0.0f, dp_hi = 0.0f;

    const int njt = it + 1;
    for (int jt = 0; jt < njt; jt++) {
        const int j0 = jt * 64;

        // issue this tile's K + VT copies
        {
            const float* kh = g_knh + gb + (size_t)j0 * D_;
            const float* kl = g_knl + gb + (size_t)j0 * D_;
            const float* vh = g_vth + gvt + j0;
            const float* vl = g_vtl + gvt + j0;
            #pragma unroll
            for (int e = tid; e < 1024; e += 128) {
                int r = e >> 4, c = (e & 15) << 2;
                cp_async16(Kh + r * 68 + c, kh + r * 64 + c);
                cp_async16(Kl + r * 68 + c, kl + r * 64 + c);
                cp_async16(VT + r * 68 + c,        vh + (size_t)r * N_ + c);
                cp_async16(VT + 4352 + r * 68 + c, vl + (size_t)r * N_ + c);
            }
            asm volatile("cp.async.commit_group;");
        }
        asm volatile("cp.async.wait_group 0;");
        __syncthreads();

        // GEMM1: S = Q . K^T  (3xTF32, pure LDS+HMMA)
        float sacc[8][4] = {};
        #pragma unroll
        for (int kk = 0; kk < 8; kk++)
            #pragma unroll
            for (int n = 0; n < 8; n++) {
                const int o0 = (n * 8 + g) * 68 + kk * 8 + l;
                uint32_t bh0 = __float_as_uint(Kh[o0]);
                uint32_t bh1 = __float_as_uint(Kh[o0 + 4]);
                uint32_t bl0 = __float_as_uint(Kl[o0]);
                uint32_t bl1 = __float_as_uint(Kl[o0 + 4]);
                mma_tf32(sacc[n], qah[kk], bh0, bh1);
                mma_tf32(sacc[n], qal[kk], bh0, bh1);
                mma_tf32(sacc[n], qah[kk], bl0, bl1);
            }
        __syncthreads();   // all warps done reading K before S is staged there

        // Epilogue: bias gather (LDG), +1, causal mask, denom partials,
        // stage fp32 S into the dead K slot (warp-private rows).
        float* Ss = Kh;
        const bool full = (jt < it);
        #pragma unroll
        for (int n = 0; n < 8; n++) {
            int jc = j0 + n * 8 + 2 * l;
            float v00, v01, v10, v11;
            if (full) {
                v00 = sacc[n][0] + 1.0f + __ldg(qlo - jc);
                v01 = sacc[n][1] + 1.0f + __ldg(qlo - (jc + 1));
                v10 = sacc[n][2] + 1.0f + __ldg(qhi - jc);
                v11 = sacc[n][3] + 1.0f + __ldg(qhi - (jc + 1));
            } else {
                v00 = (jc     <= i_lo) ? sacc[n][0] + 1.0f + __ldg(qlo - jc)       : 0.0f;
                v01 = (jc + 1 <= i_lo) ? sacc[n][1] + 1.0f + __ldg(qlo - (jc + 1)) : 0.0f;
                v10 = (jc     <= i_hi) ? sacc[n][2] + 1.0f + __ldg(qhi - jc)       : 0.0f;
                v11 = (jc + 1 <= i_hi) ? sacc[n][3] + 1.0f + __ldg(qhi - (jc + 1)) : 0.0f;
            }
            dp_lo += v00 + v01;
            dp_hi += v10 + v11;
            *reinterpret_cast<float2*>(Ss + r0 * 68 + n * 8 + 2 * l) =
                make_float2(v00, v01);
            *reinterpret_cast<float2*>(Ss + (r0 + 8) * 68 + n * 8 + 2 * l) =
                make_float2(v10, v11);
        }
        __syncwarp();

        // GEMM2: O += S . V  (A = S split on load; B = VT, K-style index)
        const float* Vh = VT;
        const float* Vl = VT + 4352;
        #pragma unroll
        for (int kk = 0; kk < 8; kk++) {
            uint32_t ah[4], al[4];
            split2(Ss[r0 * 68 + kk * 8 + l],           ah[0], al[0]);
            split2(Ss[(r0 + 8) * 68 + kk * 8 + l],     ah[1], al[1]);
            split2(Ss[r0 * 68 + kk * 8 + l + 4],       ah[2], al[2]);
            split2(Ss[(r0 + 8) * 68 + kk * 8 + l + 4], ah[3], al[3]);
            #pragma unroll
            for (int n = 0; n < 8; n++) {
                const int o0 = (n * 8 + g) * 68 + kk * 8 + l;
                uint32_t bh0 = __float_as_uint(Vh[o0]);
                uint32_t bh1 = __float_as_uint(Vh[o0 + 4]);
                uint32_t bl0 = __float_as_uint(Vl[o0]);
                uint32_t bl1 = __float_as_uint(Vl[o0 + 4]);
                mma_tf32(oacc[n], ah, bh0, bh1);
                mma_tf32(oacc[n], al, bh0, bh1);
                mma_tf32(oacc[n], ah, bl0, bl1);
            }
        }

        __syncthreads();   // VT/Ss dead before next tile's copies
    }

    // Row denominators: reduce across the 4 lanes of each quad
    dp_lo += __shfl_xor_sync(0xffffffffu, dp_lo, 1);
    dp_lo += __shfl_xor_sync(0xffffffffu, dp_lo, 2);
    dp_hi += __shfl_xor_sync(0xffffffffu, dp_hi, 1);
    dp_hi += __shfl_xor_sync(0xffffffffu, dp_hi, 2);
    const float rlo = 1.0f / dp_lo;
    const float rhi = 1.0f / dp_hi;

    float* olo = out + ((size_t)bh * N_ + i_lo) * D_;
    float* ohi = out + ((size_t)bh * N_ + i_hi) * D_;
    #pragma unroll
    for (int n = 0; n < 8; n++) {
        int dc = n * 8 + 2 * l;
        *reinterpret_cast<float2*>(olo + dc) =
            make_float2(oacc[n][0] * rlo, oacc[n][1] * rlo);
        *reinterpret_cast<float2*>(ohi + dc) =
            make_float2(oacc[n][2] * rhi, oacc[n][3] * rhi);
    }
}

// ---------------------------------------------------------------------------
extern "C" void kernel_launch(void* const* d_in, const int* in_sizes, int n_in,
                              void* d_out, int out_size) {
    const float* q   = (const float*)d_in[0];
    const float* k   = (const float*)d_in[1];
    const float* v   = (const float*)d_in[2];
    const float* dn  = (const float*)d_in[3];
    const float* rpe = (const float*)d_in[4];
    float* out = (float*)d_out;

    prep_norm_kernel<<<(2 * BH_ * N_) / 8, 256>>>(q, k);
    prep_vt_kernel<<<dim3(N_ / 64, BH_), 256>>>(v, dn);

    const int qr_smem = (128 * 68 + 64 * 68) * sizeof(float);       // 52224 B
    cudaFuncSetAttribute(qr_mma_kernel,
                         cudaFuncAttributeMaxDynamicSharedMemorySize, qr_smem);
    qr_mma_kernel<<<dim3(16, 8, BH_), 256, qr_smem>>>(rpe);

    const int mn_smem = (4 * 4352) * sizeof(float);                 // 69632 B
    cudaFuncSetAttribute(fastmax_mma_kernel,
                         cudaFuncAttributeMaxDynamicSharedMemorySize, mn_smem);
    fastmax_mma_kernel<<<dim3(16, BH_), 128, mn_smem>>>(out);
}

// round 17
// speedup vs baseline: 1.6383x; 1.2774x over previous
#include <cuda_runtime.h>
#include <cstdint>

// fastmax attention, b=4 h=16 n=1024 d=64.
// Round 16: EXACT R10 main/prep (best measured) + ONE change: qr kernel at
// 2 CTAs/SM via __launch_bounds__(256,2) + halved accumulator working set
// (n processed in two halves of 4). Arithmetic bit-identical.

#define B_  4
#define H_  16
#define N_  1024
#define D_  64
#define BH_ (B_*H_)

__device__ float g_qn [(size_t)BH_ * N_ * D_];          // fp32 normalized q
__device__ float g_knh[(size_t)BH_ * N_ * D_];          // tf32-hi of normalized k
__device__ float g_knl[(size_t)BH_ * N_ * D_];          // tf32-lo
__device__ float g_vph[(size_t)BH_ * N_ * D_];          // tf32-hi of v+0.1*noise
__device__ float g_vpl[(size_t)BH_ * N_ * D_];          // tf32-lo
__device__ float g_qr [(size_t)BH_ * N_ * N_];          // fp32 bias table (m-indexed)

// ---------------------------------------------------------------------------
__device__ __forceinline__ void split2(float x, uint32_t& hi, uint32_t& lo) {
    asm("cvt.rna.tf32.f32 %0, %1;" : "=r"(hi) : "f"(x));
    float r = x - __uint_as_float(hi);
    asm("cvt.rna.tf32.f32 %0, %1;" : "=r"(lo) : "f"(r));
}

__device__ __forceinline__ void mma_tf32(float c[4], const uint32_t a[4],
                                         uint32_t b0, uint32_t b1) {
    asm("mma.sync.aligned.m16n8k8.row.col.f32.tf32.tf32.f32 "
        "{%0,%1,%2,%3}, {%4,%5,%6,%7}, {%8,%9}, {%0,%1,%2,%3};"
        : "+f"(c[0]), "+f"(c[1]), "+f"(c[2]), "+f"(c[3])
        : "r"(a[0]), "r"(a[1]), "r"(a[2]), "r"(a[3]), "r"(b0), "r"(b1));
}

__device__ __forceinline__ void cp_async16(void* sdst, const void* gsrc) {
    uint32_t s = (uint32_t)__cvta_generic_to_shared(sdst);
    asm volatile("cp.async.cg.shared.global [%0], [%1], 16;" :: "r"(s), "l"(gsrc));
}

// ---------------------------------------------------------------------------
// prep: normalize q -> g_qn (fp32); normalize k -> split tf32 hi/lo
// ---------------------------------------------------------------------------
__global__ void prep_norm_kernel(const float* __restrict__ q,
                                 const float* __restrict__ k) {
    int gw   = (blockIdx.x * blockDim.x + threadIdx.x) >> 5;
    int lane = threadIdx.x & 31;
    const int total = BH_ * N_;
    const bool is_q = (gw < total);
    const int row = is_q ? gw : gw - total;
    const float* src = is_q ? q : k;
    const float2 v = reinterpret_cast<const float2*>(src + (size_t)row * D_)[lane];
    float ss = v.x * v.x + v.y * v.y;
    #pragma unroll
    for (int o = 16; o > 0; o >>= 1) ss += __shfl_xor_sync(0xffffffffu, ss, o);
    float inv = rsqrtf(ss);
    float x = v.x * inv, y = v.y * inv;
    if (is_q) {
        reinterpret_cast<float2*>(g_qn + (size_t)row * D_)[lane] = make_float2(x, y);
    } else {
        uint32_t xh, xl, yh, yl;
        split2(x, xh, xl);
        split2(y, yh, yl);
        reinterpret_cast<float2*>(g_knh + (size_t)row * D_)[lane] =
            make_float2(__uint_as_float(xh), __uint_as_float(yh));
        reinterpret_cast<float2*>(g_knl + (size_t)row * D_)[lane] =
            make_float2(__uint_as_float(xl), __uint_as_float(yl));
    }
}

// ---------------------------------------------------------------------------
// prep: Vp = v + 0.1*noise -> split tf32 hi/lo
// ---------------------------------------------------------------------------
__global__ void prep_v_kernel(const float* __restrict__ v,
                              const float* __restrict__ nz) {
    int i = blockIdx.x * blockDim.x + threadIdx.x;
    float4 a = reinterpret_cast<const float4*>(v)[i];
    float4 b = reinterpret_cast<const float4*>(nz)[i];
    float4 h, l;
    uint32_t th, tl;
    split2(fmaf(0.1f, b.x, a.x), th, tl); h.x = __uint_as_float(th); l.x = __uint_as_float(tl);
    split2(fmaf(0.1f, b.y, a.y), th, tl); h.y = __uint_as_float(th); l.y = __uint_as_float(tl);
    split2(fmaf(0.1f, b.z, a.z), th, tl); h.z = __uint_as_float(th); l.z = __uint_as_float(tl);
    split2(fmaf(0.1f, b.w, a.w), th, tl); h.w = __uint_as_float(th); l.w = __uint_as_float(tl);
    reinterpret_cast<float4*>(g_vph)[i] = h;
    reinterpret_cast<float4*>(g_vpl)[i] = l;
}

// ---------------------------------------------------------------------------
// QR[bh][i][m] = Qn_i . rpe2[m], 128x64 tiles via 3xTF32 mma.
// R16: __launch_bounds__(256,2) (2 CTAs/SM) with accumulators processed in
// two n-halves to fit the 128-reg cap. rpe pre-split into Rsh/Rsl (R12 body).
// ---------------------------------------------------------------------------
__global__ void __launch_bounds__(256, 2) qr_mma_kernel(const float* __restrict__ rpe) {
    const int mx = blockIdx.x, iy = blockIdx.y, bh = blockIdx.z;
    if (mx > 2 * iy + 1) return;

    extern __shared__ float sm[];
    float* Qs  = sm;              // [128][68] fp32
    float* Rsh = sm + 8704;       // [64][68] tf32-hi of rpe tile
    float* Rsl = sm + 13056;      // [64][68] tf32-lo

    const int tid = threadIdx.x;
    const int w = tid >> 5, lane = tid & 31;
    const int g = lane >> 2, l = lane & 3;
    const int i0 = iy * 128, m0 = mx * 64;

    const float* qsrc = g_qn + ((size_t)bh * N_ + i0) * D_;
    #pragma unroll
    for (int e = tid; e < 2048; e += 256) {
        int r = e >> 4, c = (e & 15) << 2;
        *reinterpret_cast<float4*>(Qs + r * 68 + c) =
            *reinterpret_cast<const float4*>(qsrc + r * 64 + c);
    }
    const float* rsrc = rpe + (size_t)(N_ - 1 + m0) * D_;
    #pragma unroll
    for (int e = tid; e < 1024; e += 256) {
        int r = e >> 4, c = (e & 15) << 2;
        float4 x = *reinterpret_cast<const float4*>(rsrc + r * 64 + c);
        float4 hh, ll;
        uint32_t th, tl;
        split2(x.x, th, tl); hh.x = __uint_as_float(th); ll.x = __uint_as_float(tl);
        split2(x.y, th, tl); hh.y = __uint_as_float(th); ll.y = __uint_as_float(tl);
        split2(x.z, th, tl); hh.z = __uint_as_float(th); ll.z = __uint_as_float(tl);
        split2(x.w, th, tl); hh.w = __uint_as_float(th); ll.w = __uint_as_float(tl);
        *reinterpret_cast<float4*>(Rsh + r * 68 + c) = hh;
        *reinterpret_cast<float4*>(Rsl + r * 68 + c) = ll;
    }
    __syncthreads();

    const int r0 = w * 16 + g;
    uint32_t qah[8][4], qal[8][4];
    #pragma unroll
    for (int kk = 0; kk < 8; kk++) {
        split2(Qs[r0 * 68 + kk * 8 + l],           qah[kk][0], qal[kk][0]);
        split2(Qs[(r0 + 8) * 68 + kk * 8 + l],     qah[kk][1], qal[kk][1]);
        split2(Qs[r0 * 68 + kk * 8 + l + 4],       qah[kk][2], qal[kk][2]);
        split2(Qs[(r0 + 8) * 68 + kk * 8 + l + 4], qah[kk][3], qal[kk][3]);
    }

    float* dst = g_qr + (size_t)bh * N_ * N_;
    const int i_lo = i0 + r0, i_hi = i_lo + 8;

    #pragma unroll
    for (int half = 0; half < 2; half++) {
        float acc[4][4] = {};
        #pragma unroll
        for (int kk = 0; kk < 8; kk++)
            #pragma unroll
            for (int nn = 0; nn < 4; nn++) {
                const int n = half * 4 + nn;
                const int o0 = (n * 8 + g) * 68 + kk * 8 + l;
                uint32_t bh0 = __float_as_uint(Rsh[o0]);
                uint32_t bh1 = __float_as_uint(Rsh[o0 + 4]);
                uint32_t bl0 = __float_as_uint(Rsl[o0]);
                uint32_t bl1 = __float_as_uint(Rsl[o0 + 4]);
                mma_tf32(acc[nn], qah[kk], bh0, bh1);
                mma_tf32(acc[nn], qal[kk], bh0, bh1);
                mma_tf32(acc[nn], qah[kk], bl0, bl1);
            }
        #pragma unroll
        for (int nn = 0; nn < 4; nn++) {
            const int n = half * 4 + nn;
            int mc = m0 + n * 8 + 2 * l;
            *reinterpret_cast<float2*>(dst + (size_t)i_lo * N_ + mc) =
                make_float2(acc[nn][0], acc[nn][1]);
            *reinterpret_cast<float2*>(dst + (size_t)i_hi * N_ + mc) =
                make_float2(acc[nn][2], acc[nn][3]);
        }
    }
}

// ---------------------------------------------------------------------------
// Main fused attention: block = (bh, 64-row i-tile), 4 warps, 2 CTAs/SM.
// (byte-identical to R10's proven main kernel)
// ---------------------------------------------------------------------------
__global__ void __launch_bounds__(128, 2) fastmax_mma_kernel(float* __restrict__ out) {
    extern __shared__ float sm[];
    float* Qs = sm;                  // [64][68], reused as Ss after Q extract
    float* Kh = sm + 4352;           // [64][68]
    float* Kl = sm + 8704;           // [64][68]
    float* Vh = sm + 13056;          // [64][72]
    float* Vl = sm + 17664;          // [64][72]  total 22272 floats = 89088 B

    const int it = 15 - blockIdx.x;  // heavy tiles first
    const int bh = blockIdx.y;
    const int i0 = it * 64;

    const int tid = threadIdx.x;
    const int w = tid >> 5, lane = tid & 31;
    const int g = lane >> 2, l = lane & 3;
    const int r0 = w * 16 + g;

    // Load Q strip (64 rows), extract per-warp A fragments, pre-split hi/lo
    const float* qsrc = g_qn + ((size_t)bh * N_ + i0) * D_;
    #pragma unroll
    for (int e = tid; e < 1024; e += 128) {
        int r = e >> 4, c = (e & 15) << 2;
        *reinterpret_cast<float4*>(Qs + r * 68 + c) =
            *reinterpret_cast<const float4*>(qsrc + r * 64 + c);
    }
    __syncthreads();

    uint32_t qah[8][4], qal[8][4];
    #pragma unroll
    for (int kk = 0; kk < 8; kk++) {
        split2(Qs[r0 * 68 + kk * 8 + l],           qah[kk][0], qal[kk][0]);
        split2(Qs[(r0 + 8) * 68 + kk * 8 + l],     qah[kk][1], qal[kk][1]);
        split2(Qs[r0 * 68 + kk * 8 + l + 4],       qah[kk][2], qal[kk][2]);
        split2(Qs[(r0 + 8) * 68 + kk * 8 + l + 4], qah[kk][3], qal[kk][3]);
    }

    const int i_lo = i0 + r0, i_hi = i_lo + 8;
    const float* qlo = g_qr + (size_t)bh * N_ * N_ + (size_t)i_lo * (N_ + 1);
    const float* qhi = g_qr + (size_t)bh * N_ * N_ + (size_t)i_hi * (N_ + 1);

    float oacc[8][4] = {};
    float dp_lo = 0.0f, dp_hi = 0.0f;
    float* Ss = Qs;   // warp-private rows -> __syncwarp suffices

    __syncthreads();  // Q fragment extraction done before Ss reuse

    const int njt = it + 1;
    for (int jt = 0; jt < njt; jt++) {
        const int j0 = jt * 64;

        // issue this tile's K/V copies into the single buffer
        {
            const size_t base = ((size_t)bh * N_ + j0) * D_;
            const float* kh = g_knh + base;
            const float* kl = g_knl + base;
            const float* vh = g_vph + base;
            const float* vl = g_vpl + base;
            #pragma unroll
            for (int e = tid; e < 1024; e += 128) {
                int r = e >> 4, c = (e & 15) << 2;
                cp_async16(Kh + r * 68 + c, kh + r * 64 + c);
                cp_async16(Kl + r * 68 + c, kl + r * 64 + c);
                cp_async16(Vh + r * 72 + c, vh + r * 64 + c);
                cp_async16(Vl + r * 72 + c, vl + r * 64 + c);
            }
            asm volatile("cp.async.commit_group;");
        }

        // bias gather overlaps with the cp.async in flight
        const bool full = (jt < it);
        float qrv[8][4];
        #pragma unroll
        for (int n = 0; n < 8; n++) {
            int jc = j0 + n * 8 + 2 * l;
            if (full) {
                qrv[n][0] = __ldg(qlo - jc);
                qrv[n][1] = __ldg(qlo - (jc + 1));
                qrv[n][2] = __ldg(qhi - jc);
                qrv[n][3] = __ldg(qhi - (jc + 1));
            } else {
                qrv[n][0] = (jc     <= i_lo) ? __ldg(qlo - jc)       : 0.0f;
                qrv[n][1] = (jc + 1 <= i_lo) ? __ldg(qlo - (jc + 1)) : 0.0f;
                qrv[n][2] = (jc     <= i_hi) ? __ldg(qhi - jc)       : 0.0f;
                qrv[n][3] = (jc + 1 <= i_hi) ? __ldg(qhi - (jc + 1)) : 0.0f;
            }
        }

        asm volatile("cp.async.wait_group 0;");
        __syncthreads();

        // GEMM1: S = Q . K^T  (3xTF32, K pre-split, pure LDS+HMMA)
        float sacc[8][4] = {};
        #pragma unroll
        for (int kk = 0; kk < 8; kk++)
            #pragma unroll
            for (int n = 0; n < 8; n++) {
                const int o0 = (n * 8 + g) * 68 + kk * 8 + l;
                uint32_t bh0 = __float_as_uint(Kh[o0]);
                uint32_t bh1 = __float_as_uint(Kh[o0 + 4]);
                uint32_t bl0 = __float_as_uint(Kl[o0]);
                uint32_t bl1 = __float_as_uint(Kl[o0 + 4]);
                mma_tf32(sacc[n], qah[kk], bh0, bh1);
                mma_tf32(sacc[n], qal[kk], bh0, bh1);
                mma_tf32(sacc[n], qah[kk], bl0, bl1);
            }

        // Epilogue: +1, bias, causal mask, denom partials, stage fp32 S
        #pragma unroll
        for (int n = 0; n < 8; n++) {
            int jc = j0 + n * 8 + 2 * l;
            float v00, v01, v10, v11;
            if (full) {
                v00 = sacc[n][0] + 1.0f + qrv[n][0];
                v01 = sacc[n][1] + 1.0f + qrv[n][1];
                v10 = sacc[n][2] + 1.0f + qrv[n][2];
                v11 = sacc[n][3] + 1.0f + qrv[n][3];
            } else {
                v00 = (jc     <= i_lo) ? sacc[n][0] + 1.0f + qrv[n][0] : 0.0f;
                v01 = (jc + 1 <= i_lo) ? sacc[n][1] + 1.0f + qrv[n][1] : 0.0f;
                v10 = (jc     <= i_hi) ? sacc[n][2] + 1.0f + qrv[n][2] : 0.0f;
                v11 = (jc + 1 <= i_hi) ? sacc[n][3] + 1.0f + qrv[n][3] : 0.0f;
            }
            dp_lo += v00 + v01;
            dp_hi += v10 + v11;
            *reinterpret_cast<float2*>(Ss + r0 * 68 + n * 8 + 2 * l) =
                make_float2(v00, v01);
            *reinterpret_cast<float2*>(Ss + (r0 + 8) * 68 + n * 8 + 2 * l) =
                make_float2(v10, v11);
        }
        __syncwarp();

        // GEMM2: O += S . V  (3xTF32; A = S strip split on load, V pre-split)
        #pragma unroll
        for (int kk = 0; kk < 8; kk++) {
            uint32_t ah[4], al[4];
            split2(Ss[r0 * 68 + kk * 8 + l],           ah[0], al[0]);
            split2(Ss[(r0 + 8) * 68 + kk * 8 + l],     ah[1], al[1]);
            split2(Ss[r0 * 68 + kk * 8 + l + 4],       ah[2], al[2]);
            split2(Ss[(r0 + 8) * 68 + kk * 8 + l + 4], ah[3], al[3]);
            #pragma unroll
            for (int n = 0; n < 8; n++) {
                const int p0 = (kk * 8 + l) * 72 + n * 8 + g;
                const int p1 = (kk * 8 + l + 4) * 72 + n * 8 + g;
                uint32_t bh0 = __float_as_uint(Vh[p0]);
                uint32_t bh1 = __float_as_uint(Vh[p1]);
                uint32_t bl0 = __float_as_uint(Vl[p0]);
                uint32_t bl1 = __float_as_uint(Vl[p1]);
                mma_tf32(oacc[n], ah, bh0, bh1);
                mma_tf32(oacc[n], al, bh0, bh1);
                mma_tf32(oacc[n], ah, bl0, bl1);
            }
        }

        __syncthreads();   // all warps done reading K/V before next overwrite
    }

    // Row denominators: reduce across the 4 lanes of each quad
    dp_lo += __shfl_xor_sync(0xffffffffu, dp_lo, 1);
    dp_lo += __shfl_xor_sync(0xffffffffu, dp_lo, 2);
    dp_hi += __shfl_xor_sync(0xffffffffu, dp_hi, 1);
    dp_hi += __shfl_xor_sync(0xffffffffu, dp_hi, 2);
    const float rlo = 1.0f / dp_lo;
    const float rhi = 1.0f / dp_hi;

    float* olo = out + ((size_t)bh * N_ + i_lo) * D_;
    float* ohi = out + ((size_t)bh * N_ + i_hi) * D_;
    #pragma unroll
    for (int n = 0; n < 8; n++) {
        int dc = n * 8 + 2 * l;
        *reinterpret_cast<float2*>(olo + dc) =
            make_float2(oacc[n][0] * rlo, oacc[n][1] * rlo);
        *reinterpret_cast<float2*>(ohi + dc) =
            make_float2(oacc[n][2] * rhi, oacc[n][3] * rhi);
    }
}

// ---------------------------------------------------------------------------
extern "C" void kernel_launch(void* const* d_in, const int* in_sizes, int n_in,
                              void* d_out, int out_size) {
    const float* q   = (const float*)d_in[0];
    const float* k   = (const float*)d_in[1];
    const float* v   = (const float*)d_in[2];
    const float* dn  = (const float*)d_in[3];
    const float* rpe = (const float*)d_in[4];
    float* out = (float*)d_out;

    prep_norm_kernel<<<(2 * BH_ * N_) / 8, 256>>>(q, k);
    prep_v_kernel<<<(BH_ * N_ * D_ / 4) / 256, 256>>>(v, dn);

    const int qr_smem = (8704 + 2 * 4352) * sizeof(float);          // 69632 B
    cudaFuncSetAttribute(qr_mma_kernel,
                         cudaFuncAttributeMaxDynamicSharedMemorySize, qr_smem);
    qr_mma_kernel<<<dim3(16, 8, BH_), 256, qr_smem>>>(rpe);

    const int mn_smem = 22272 * sizeof(float);                      // 89088 B
    cudaFuncSetAttribute(fastmax_mma_kernel,
                         cudaFuncAttributeMaxDynamicSharedMemorySize, mn_smem);
    fastmax_mma_kernel<<<dim3(16, BH_), 128, mn_smem>>>(out);
}